// round 11
// baseline (speedup 1.0000x reference)
#include <cuda_runtime.h>

// OrbitalAEVComputer: coefficients [64,256,45] f32 -> out [64,256,4608] f32
// Per (conf,atom): 12 AOVs (4 p + 8 reordered d), radial 12*32, angular 66*8*8.

#define NBLOCKS (64 * 256)
#define OUT_STRIDE 4608
#define NPAIR 66

// cos/sin of shfZ = linspace(0.19634954, 2.94524311, 8)  (odd multiples of pi/16)
__constant__ float COSZ[8] = {
     0.98078528f,  0.83146961f,  0.55557023f,  0.19509032f,
    -0.19509032f, -0.55557023f, -0.83146961f, -0.98078528f
};
__constant__ float SINZ[8] = {
     0.19509032f,  0.55557023f,  0.83146961f,  0.98078528f,
     0.98078528f,  0.83146961f,  0.55557023f,  0.19509032f
};

// triu_indices(12, k=1), i-major
__constant__ unsigned char IU[NPAIR] = {
    0,0,0,0,0,0,0,0,0,0,0,
    1,1,1,1,1,1,1,1,1,1,
    2,2,2,2,2,2,2,2,2,
    3,3,3,3,3,3,3,3,
    4,4,4,4,4,4,4,
    5,5,5,5,5,5,
    6,6,6,6,6,
    7,7,7,7,
    8,8,8,
    9,9,
    10
};
__constant__ unsigned char JU[NPAIR] = {
    1,2,3,4,5,6,7,8,9,10,11,
    2,3,4,5,6,7,8,9,10,11,
    3,4,5,6,7,8,9,10,11,
    4,5,6,7,8,9,10,11,
    5,6,7,8,9,10,11,
    6,7,8,9,10,11,
    7,8,9,10,11,
    8,9,10,11,
    9,10,11,
    10,11,
    11
};

// 256-bit store (sm_100+): one instruction writes a full 32B row.
__device__ __forceinline__ void stg256(float* p,
                                       float v0, float v1, float v2, float v3,
                                       float v4, float v5, float v6, float v7)
{
    asm volatile("st.global.v8.f32 [%0], {%1,%2,%3,%4,%5,%6,%7,%8};"
                 :: "l"(p), "f"(v0), "f"(v1), "f"(v2), "f"(v3),
                           "f"(v4), "f"(v5), "f"(v6), "f"(v7)
                 : "memory");
}

__device__ __forceinline__ float pow32half1p(float cosd)
{
    float b = fmaf(0.5f, cosd, 0.5f);   // (1+cosd)/2 in [0,1]
    float q = b * b;                    // ^2
    q *= q;                             // ^4
    q *= q;                             // ^8
    q *= q;                             // ^16
    q *= q;                             // ^32
    return 2.0f * q;
}

__global__ __launch_bounds__(128, 9)
void orbital_aev_kernel(const float* __restrict__ coeff, float* __restrict__ out)
{
    __shared__ float  dsh[12];
    __shared__ float  nvsh[12][3];
    __shared__ float4 pairsh[NPAIR];   // (cz = 0.95*cos, sz = sqrt(1-cz^2), avdist, 0)

    const int t = threadIdx.x;
    const float* __restrict__ c = coeff + (size_t)blockIdx.x * 45;
    float* __restrict__ o = out + (size_t)blockIdx.x * OUT_STRIDE;

    // ---- Build 12 AOVs: dist + normalized vectors into SMEM ----
    if (t < 12) {
        float x, y, z;
        if (t < 4) {
            int b = 9 + 3 * t;
            x = c[b]; y = c[b + 1]; z = c[b + 2];
        } else {
            int r = (t - 4) >> 1;
            int b = 21 + 6 * r;
            if (((t - 4) & 1) == 0) {        // d row picks [0,2,5]
                x = c[b];     y = c[b + 2]; z = c[b + 5];
            } else {                          // then [4,3,1]
                x = c[b + 4]; y = c[b + 3]; z = c[b + 1];
            }
        }
        float s = x * x + y * y + z * z;
        float inv, d;
        if (s > 1e-24f) { inv = rsqrtf(s); d = s * inv; }
        else            { inv = 0.0f;      d = 0.0f;    }
        dsh[t] = d;
        nvsh[t][0] = x * inv;
        nvsh[t][1] = y * inv;
        nvsh[t][2] = z * inv;
    }
    __syncthreads();

    // ---- Middle phase: DISJOINT thread ranges run concurrently. ----
    // Threads [0,66): pair terms cz/sz/avdist into SMEM.
    // Threads [66,114): radial outputs (s_aev == r_aev; 48 x STG.256).
    if (t < NPAIR) {
        int i = IU[t], j = JU[t];
        float cc = nvsh[i][0] * nvsh[j][0]
                 + nvsh[i][1] * nvsh[j][1]
                 + nvsh[i][2] * nvsh[j][2];
        float cz = 0.95f * cc;
        float sz = sqrtf(fmaxf(0.0f, 1.0f - cz * cz));
        float av = 0.5f * (dsh[i] + dsh[j]);
        pairsh[t] = make_float4(cz, sz, av, 0.0f);
    } else if (t < NPAIR + 48) {
        int r   = t - NPAIR;
        int aov = r >> 2;
        int q   = r & 3;
        float d  = dsh[aov];
        int   kb = (q & 1) << 3;
        float v[8];
        #pragma unroll
        for (int j = 0; j < 8; j++) {
            float u = d - (0.5f + 0.2f * (float)(kb + j));
            v[j] = __expf(-16.0f * u * u);
        }
        stg256(o + (aov << 5) + (q << 3),
               v[0], v[1], v[2], v[3], v[4], v[5], v[6], v[7]);
    }
    __syncthreads();

    // ---- Angular: 264 tasks; task m owns pair p = m>>2 and TWO z-rows (zq, zq+4),
    //      so the 8 factor2 exps are computed once per 2 output rows (halves the
    //      redundant MUFU work vs one-row tasks). zq = m&3 is thread-invariant.
    //      Stores stay dense: rows 8p+zq from consecutive lanes give 4-lane
    //      contiguous 128B chunks -> minimal 8 wavefronts per STG.256. ----
    const int   zq    = t & 3;
    const float cosz0 = COSZ[zq],     sinz0 = SINZ[zq];
    const float cosz1 = COSZ[zq + 4], sinz1 = SINZ[zq + 4];

    #pragma unroll
    for (int iter = 0; iter < 3; iter++) {
        int m = t + 128 * iter;
        if (iter < 2 || t < 8) {          // 264 = 128 + 128 + 8
            int p = m >> 2;
            float4 cs = pairsh[p];        // 4-way broadcast LDS.128

            // factor2 once per pair-task: shfA = 0.5 + (3/7)*a
            float av = cs.z;
            float f2v[8];
            #pragma unroll
            for (int a = 0; a < 8; a++) {
                float ua = av - (0.5f + (3.0f / 7.0f) * (float)a);
                f2v[a] = __expf(-8.0f * ua * ua);
            }

            // factor1 for the two owned z rows (exact cos-difference identity)
            float g0 = pow32half1p(fmaf(cs.x, cosz0, cs.y * sinz0));
            float g1 = pow32half1p(fmaf(cs.x, cosz1, cs.y * sinz1));

            float* d0 = o + 384 + (((p << 3) + zq) << 3);
            stg256(d0,
                   g0 * f2v[0], g0 * f2v[1], g0 * f2v[2], g0 * f2v[3],
                   g0 * f2v[4], g0 * f2v[5], g0 * f2v[6], g0 * f2v[7]);
            stg256(d0 + 32,                    // row +4 -> +32 floats
                   g1 * f2v[0], g1 * f2v[1], g1 * f2v[2], g1 * f2v[3],
                   g1 * f2v[4], g1 * f2v[5], g1 * f2v[6], g1 * f2v[7]);
        }
    }
}

extern "C" void kernel_launch(void* const* d_in, const int* in_sizes, int n_in,
                              void* d_out, int out_size)
{
    const float* coeff = (const float*)d_in[0];
    float* out = (float*)d_out;
    orbital_aev_kernel<<<NBLOCKS, 128>>>(coeff, out);
}